// round 1
// baseline (speedup 1.0000x reference)
#include <cuda_runtime.h>
#include <math.h>

#define BATCH 2
#define CH    512
#define NH    8
#define HD    64
#define HW    4096          // 64*64 tokens
#define NG    8             // groups
#define CPG   (CH/NG)       // 64 channels per group
#define EPS   1e-5f

// ---------------- scratch (static device globals; no allocations) ----------
__device__ float g_xnorm[(size_t)BATCH*CH*HW];              // 16 MB
__device__ float g_qkv[(size_t)BATCH*3*CH*HW];              // 50 MB
__device__ float g_scores[(size_t)BATCH*NH*HW*HW];          // 1 GiB
__device__ float g_att[(size_t)BATCH*CH*HW];                // 16 MB

// ---------------- reductions ----------------
__device__ __forceinline__ float warpSum(float v) {
    #pragma unroll
    for (int o = 16; o > 0; o >>= 1) v += __shfl_xor_sync(0xffffffffu, v, o);
    return v;
}
__device__ __forceinline__ float warpMax(float v) {
    #pragma unroll
    for (int o = 16; o > 0; o >>= 1) v = fmaxf(v, __shfl_xor_sync(0xffffffffu, v, o));
    return v;
}

// ---------------- 1) GroupNorm ----------------
// one block per (batch, group); 512 threads
__global__ void gn_kernel(const float* __restrict__ x,
                          const float* __restrict__ w,
                          const float* __restrict__ b) {
    int bb = blockIdx.x / NG;
    int g  = blockIdx.x % NG;
    size_t base = ((size_t)bb*CH + (size_t)g*CPG) * HW;
    const float4* x4 = (const float4*)(x + base);
    float4*       o4 = (float4*)(g_xnorm + base);
    const int NV = CPG*HW/4;   // 65536 float4

    float s = 0.f, s2 = 0.f;
    for (int i = threadIdx.x; i < NV; i += blockDim.x) {
        float4 t = x4[i];
        s  += t.x + t.y + t.z + t.w;
        s2 += t.x*t.x + t.y*t.y + t.z*t.z + t.w*t.w;
    }
    __shared__ float shs[16], shs2[16];
    s = warpSum(s); s2 = warpSum(s2);
    int wid = threadIdx.x >> 5, lane = threadIdx.x & 31;
    if (lane == 0) { shs[wid] = s; shs2[wid] = s2; }
    __syncthreads();
    if (threadIdx.x == 0) {
        float a = 0.f, c = 0.f;
        int nw = blockDim.x >> 5;
        for (int i = 0; i < nw; i++) { a += shs[i]; c += shs2[i]; }
        shs[0] = a; shs2[0] = c;
    }
    __syncthreads();
    float total  = shs[0], total2 = shs2[0];
    const float invN = 1.f / (float)(CPG*HW);
    float mean = total * invN;
    float var  = total2 * invN - mean*mean;
    float rstd = rsqrtf(var + EPS);

    for (int i = threadIdx.x; i < NV; i += blockDim.x) {
        float4 t = x4[i];
        int ch = g*CPG + (i*4) / HW;       // all 4 elements share channel (HW%4==0)
        float sc = w[ch] * rstd;
        float bo = b[ch] - mean * sc;
        float4 r;
        r.x = t.x*sc + bo; r.y = t.y*sc + bo;
        r.z = t.z*sc + bo; r.w = t.w*sc + bo;
        o4[i] = r;
    }
}

// ---------------- generic NN GEMM: C = A[M,K] * B[K,N] + bias (+resid) -----
// 64x64 tile, BK=16, 256 threads, 4x4 microtile
__global__ __launch_bounds__(256)
void gemm_nn_kernel(const float* __restrict__ A,
                    const float* __restrict__ Bm,
                    const float* __restrict__ bias,
                    const float* __restrict__ resid,
                    float* __restrict__ Cout,
                    int M, int K, int N,
                    size_t strideB, size_t strideC, size_t strideR) {
    __shared__ float As[16][64];
    __shared__ float Bs[16][64];
    const float* Bp = Bm + (size_t)blockIdx.z * strideB;
    float*       Cp = Cout + (size_t)blockIdx.z * strideC;
    const float* Rp = resid ? resid + (size_t)blockIdx.z * strideR : nullptr;
    int m0 = blockIdx.y * 64, n0 = blockIdx.x * 64;
    int tid = threadIdx.x;
    int tx = tid & 15, ty = tid >> 4;
    float acc[4][4] = {};

    for (int k0 = 0; k0 < K; k0 += 16) {
        #pragma unroll
        for (int l = tid; l < 1024; l += 256) {
            int r = l >> 4, ck = l & 15;
            As[ck][r] = A[(size_t)(m0 + r)*K + k0 + ck];
        }
        #pragma unroll
        for (int l = tid; l < 1024; l += 256) {
            int r = l >> 6, cn = l & 63;
            Bs[r][cn] = Bp[(size_t)(k0 + r)*N + n0 + cn];
        }
        __syncthreads();
        #pragma unroll
        for (int k = 0; k < 16; k++) {
            float a[4], bb[4];
            #pragma unroll
            for (int i = 0; i < 4; i++) a[i]  = As[k][ty*4 + i];
            #pragma unroll
            for (int j = 0; j < 4; j++) bb[j] = Bs[k][tx*4 + j];
            #pragma unroll
            for (int i = 0; i < 4; i++)
                #pragma unroll
                for (int j = 0; j < 4; j++)
                    acc[i][j] += a[i] * bb[j];
        }
        __syncthreads();
    }
    #pragma unroll
    for (int i = 0; i < 4; i++) {
        int m = m0 + ty*4 + i;
        float bi = bias[m];
        #pragma unroll
        for (int j = 0; j < 4; j++) {
            int n = n0 + tx*4 + j;
            float v = acc[i][j] + bi;
            if (Rp) v += Rp[(size_t)m*N + n];
            Cp[(size_t)m*N + n] = v;
        }
    }
}

// ---------------- 3) scores S[n,m] = sum_d Q[d,n] K[d,m] * scale ----------
__global__ __launch_bounds__(256)
void scores_kernel() {
    int bh = blockIdx.z;
    int b  = bh / NH, h = bh % NH;
    const float* Q  = g_qkv + ((size_t)b*3*CH + (size_t)h*HD) * HW;
    const float* Kp = g_qkv + ((size_t)b*3*CH + CH + (size_t)h*HD) * HW;
    float* S = g_scores + (size_t)bh * HW * HW;
    int n0 = blockIdx.y * 64, m0 = blockIdx.x * 64;
    __shared__ float Qs[16][64];
    __shared__ float Ks[16][64];
    int tid = threadIdx.x;
    int tx = tid & 15, ty = tid >> 4;
    float acc[4][4] = {};

    #pragma unroll
    for (int d0 = 0; d0 < HD; d0 += 16) {
        #pragma unroll
        for (int l = tid; l < 1024; l += 256) {
            int r = l >> 6, c = l & 63;
            Qs[r][c] = Q[(size_t)(d0 + r)*HW + n0 + c];
        }
        #pragma unroll
        for (int l = tid; l < 1024; l += 256) {
            int r = l >> 6, c = l & 63;
            Ks[r][c] = Kp[(size_t)(d0 + r)*HW + m0 + c];
        }
        __syncthreads();
        #pragma unroll
        for (int k = 0; k < 16; k++) {
            float a[4], bb[4];
            #pragma unroll
            for (int i = 0; i < 4; i++) a[i]  = Qs[k][ty*4 + i];
            #pragma unroll
            for (int j = 0; j < 4; j++) bb[j] = Ks[k][tx*4 + j];
            #pragma unroll
            for (int i = 0; i < 4; i++)
                #pragma unroll
                for (int j = 0; j < 4; j++)
                    acc[i][j] += a[i] * bb[j];
        }
        __syncthreads();
    }
    const float scale = 0.125f;   // 64^-0.5
    #pragma unroll
    for (int i = 0; i < 4; i++) {
        int n = n0 + ty*4 + i;
        #pragma unroll
        for (int j = 0; j < 4; j++) {
            int m = m0 + tx*4 + j;
            S[(size_t)n*HW + m] = acc[i][j] * scale;
        }
    }
}

// ---------------- 4) row softmax over 4096 cols ----------------
__global__ __launch_bounds__(256)
void softmax_kernel() {
    float* S = g_scores + (size_t)blockIdx.x * HW;
    float4* S4 = (float4*)S;
    int tid = threadIdx.x;
    float4 v[4];
    float mx = -1e30f;
    #pragma unroll
    for (int i = 0; i < 4; i++) {
        v[i] = S4[tid + i*256];
        mx = fmaxf(mx, fmaxf(fmaxf(v[i].x, v[i].y), fmaxf(v[i].z, v[i].w)));
    }
    __shared__ float sh[8];
    mx = warpMax(mx);
    int wid = tid >> 5, lane = tid & 31;
    if (lane == 0) sh[wid] = mx;
    __syncthreads();
    if (tid == 0) {
        float a = sh[0];
        for (int i = 1; i < 8; i++) a = fmaxf(a, sh[i]);
        sh[0] = a;
    }
    __syncthreads();
    mx = sh[0];
    __syncthreads();

    float sum = 0.f;
    #pragma unroll
    for (int i = 0; i < 4; i++) {
        v[i].x = expf(v[i].x - mx); v[i].y = expf(v[i].y - mx);
        v[i].z = expf(v[i].z - mx); v[i].w = expf(v[i].w - mx);
        sum += v[i].x + v[i].y + v[i].z + v[i].w;
    }
    sum = warpSum(sum);
    if (lane == 0) sh[wid] = sum;
    __syncthreads();
    if (tid == 0) {
        float a = 0.f;
        for (int i = 0; i < 8; i++) a += sh[i];
        sh[0] = a;
    }
    __syncthreads();
    float inv = 1.f / sh[0];
    #pragma unroll
    for (int i = 0; i < 4; i++) {
        v[i].x *= inv; v[i].y *= inv; v[i].z *= inv; v[i].w *= inv;
        S4[tid + i*256] = v[i];
    }
}

// ---------------- 5) O[d,n] = sum_m V[d,m] * P[n,m] ----------------
__global__ __launch_bounds__(256)
void pv_kernel() {
    int bh = blockIdx.y;
    int b  = bh / NH, h = bh % NH;
    const float* V = g_qkv + ((size_t)b*3*CH + 2*CH + (size_t)h*HD) * HW;
    const float* P = g_scores + (size_t)bh * HW * HW;
    float* O = g_att + ((size_t)b*CH + (size_t)h*HD) * HW;
    int n0 = blockIdx.x * 64;
    __shared__ float Vs[16][65];
    __shared__ float Ps[16][65];
    int tid = threadIdx.x;
    int tx = tid & 15, ty = tid >> 4;
    float acc[4][4] = {};

    for (int m0 = 0; m0 < HW; m0 += 16) {
        #pragma unroll
        for (int l = tid; l < 1024; l += 256) {
            int r = l >> 4, cm = l & 15;           // r: d row, cm: m col
            Vs[cm][r] = V[(size_t)r*HW + m0 + cm];
        }
        #pragma unroll
        for (int l = tid; l < 1024; l += 256) {
            int r = l >> 4, cm = l & 15;           // r: n row, cm: m col
            Ps[cm][r] = P[(size_t)(n0 + r)*HW + m0 + cm];
        }
        __syncthreads();
        #pragma unroll
        for (int k = 0; k < 16; k++) {
            float a[4], bb[4];
            #pragma unroll
            for (int i = 0; i < 4; i++) a[i]  = Vs[k][ty*4 + i];   // d
            #pragma unroll
            for (int j = 0; j < 4; j++) bb[j] = Ps[k][tx*4 + j];   // n
            #pragma unroll
            for (int i = 0; i < 4; i++)
                #pragma unroll
                for (int j = 0; j < 4; j++)
                    acc[i][j] += a[i] * bb[j];
        }
        __syncthreads();
    }
    #pragma unroll
    for (int i = 0; i < 4; i++) {
        int d = ty*4 + i;
        #pragma unroll
        for (int j = 0; j < 4; j++) {
            int n = n0 + tx*4 + j;
            O[(size_t)d*HW + n] = acc[i][j];
        }
    }
}

// ---------------- launch ----------------
extern "C" void kernel_launch(void* const* d_in, const int* in_sizes, int n_in,
                              void* d_out, int out_size) {
    const float* x      = (const float*)d_in[0];
    const float* norm_w = (const float*)d_in[1];
    const float* norm_b = (const float*)d_in[2];
    const float* qkv_w  = (const float*)d_in[3];
    const float* qkv_b  = (const float*)d_in[4];
    const float* proj_w = (const float*)d_in[5];
    const float* proj_b = (const float*)d_in[6];
    float* out = (float*)d_out;

    void *p_xnorm, *p_qkv, *p_att;
    cudaGetSymbolAddress(&p_xnorm, g_xnorm);
    cudaGetSymbolAddress(&p_qkv,   g_qkv);
    cudaGetSymbolAddress(&p_att,   g_att);
    const float* xn  = (const float*)p_xnorm;
    float*       qkv = (float*)p_qkv;
    const float* att = (const float*)p_att;

    // 1) GroupNorm
    gn_kernel<<<BATCH*NG, 512>>>(x, norm_w, norm_b);

    // 2) QKV = qkv_w[1536,512] @ x_norm[b,512,4096] + qkv_b
    gemm_nn_kernel<<<dim3(HW/64, 3*CH/64, BATCH), 256>>>(
        qkv_w, xn, qkv_b, nullptr, qkv,
        3*CH, CH, HW,
        (size_t)CH*HW, (size_t)3*CH*HW, 0);

    // 3) S = (Q^T K) * hd^-0.5
    scores_kernel<<<dim3(HW/64, HW/64, BATCH*NH), 256>>>();

    // 4) softmax rows
    softmax_kernel<<<BATCH*NH*HW, 256>>>();

    // 5) O = V @ P^T
    pv_kernel<<<dim3(HW/64, BATCH*NH), 256>>>();

    // 6) out = proj_w @ O + proj_b + x
    gemm_nn_kernel<<<dim3(HW/64, CH/64, BATCH), 256>>>(
        proj_w, att, proj_b, x, out,
        CH, CH, HW,
        (size_t)CH*HW, (size_t)CH*HW, (size_t)CH*HW);
}

// round 2
// speedup vs baseline: 5.2184x; 5.2184x over previous
#include <cuda_runtime.h>
#include <cuda_bf16.h>
#include <math.h>
#include <stdint.h>

#define BATCH 2
#define CH    512
#define NH    8
#define HD    64
#define HW    4096
#define NG    8
#define CPG   64
#define EPS   1e-5f
#define LOG2E 1.4426950408889634f
#define QSCALE (0.125f * LOG2E)

// ---------------- scratch ----------------
__device__ __nv_bfloat16 g_xn[(size_t)BATCH*HW*CH];   // x_norm^T  [b][n][c]
__device__ __nv_bfloat16 g_q[(size_t)BATCH*NH*HW*HD]; // [bh][n][d] (scaled by QSCALE)
__device__ __nv_bfloat16 g_k[(size_t)BATCH*NH*HW*HD]; // [bh][m][d]
__device__ __nv_bfloat16 g_v[(size_t)BATCH*NH*HD*HW]; // [bh][d][m]
__device__ __nv_bfloat16 g_o[(size_t)BATCH*HW*CH];    // attention out [b][n][c]

// ---------------- helpers ----------------
__device__ __forceinline__ float warpSum(float v) {
    #pragma unroll
    for (int o = 16; o > 0; o >>= 1) v += __shfl_xor_sync(0xffffffffu, v, o);
    return v;
}
__device__ __forceinline__ float ex2f(float x) {
    float r; asm("ex2.approx.ftz.f32 %0, %1;" : "=f"(r) : "f"(x)); return r;
}
__device__ __forceinline__ uint32_t packbf(float a, float b) {
    __nv_bfloat162 h = __floats2bfloat162_rn(a, b);
    return *(uint32_t*)&h;
}
__device__ __forceinline__ uint32_t ldsu32(const __nv_bfloat16* p) {
    return *(const uint32_t*)p;
}
__device__ __forceinline__ void mma16816(float c[4], const uint32_t a[4],
                                         uint32_t b0, uint32_t b1) {
    asm volatile(
        "mma.sync.aligned.m16n8k16.row.col.f32.bf16.bf16.f32 "
        "{%0,%1,%2,%3}, {%4,%5,%6,%7}, {%8,%9}, {%0,%1,%2,%3};"
        : "+f"(c[0]), "+f"(c[1]), "+f"(c[2]), "+f"(c[3])
        : "r"(a[0]), "r"(a[1]), "r"(a[2]), "r"(a[3]), "r"(b0), "r"(b1));
}

// ---------------- 1) GroupNorm -> bf16 transposed [b][n][c] ----------------
__global__ void gn_kernel(const float* __restrict__ x,
                          const float* __restrict__ w,
                          const float* __restrict__ b) {
    int bb = blockIdx.x / NG;
    int g  = blockIdx.x % NG;
    size_t base = ((size_t)bb*CH + (size_t)g*CPG) * HW;
    const float4* x4 = (const float4*)(x + base);
    const int NV = CPG*HW/4;

    float s = 0.f, s2 = 0.f;
    for (int i = threadIdx.x; i < NV; i += blockDim.x) {
        float4 t = x4[i];
        s  += t.x + t.y + t.z + t.w;
        s2 += t.x*t.x + t.y*t.y + t.z*t.z + t.w*t.w;
    }
    __shared__ float shs[16], shs2[16];
    s = warpSum(s); s2 = warpSum(s2);
    int wid = threadIdx.x >> 5, lane = threadIdx.x & 31;
    if (lane == 0) { shs[wid] = s; shs2[wid] = s2; }
    __syncthreads();
    if (threadIdx.x == 0) {
        float a = 0.f, c = 0.f;
        for (int i = 0; i < (int)(blockDim.x >> 5); i++) { a += shs[i]; c += shs2[i]; }
        shs[0] = a; shs2[0] = c;
    }
    __syncthreads();
    const float invN = 1.f / (float)(CPG*HW);
    float mean = shs[0] * invN;
    float var  = shs2[0] * invN - mean*mean;
    float rstd = rsqrtf(var + EPS);

    __nv_bfloat16* outp = g_xn + (size_t)bb*HW*CH;
    for (int i = threadIdx.x; i < NV; i += blockDim.x) {
        float4 t = x4[i];
        int ch = g*CPG + (i*4) / HW;
        int n  = (i*4) % HW;
        float sc = w[ch] * rstd;
        float bo = b[ch] - mean * sc;
        outp[(size_t)(n+0)*CH + ch] = __float2bfloat16_rn(t.x*sc + bo);
        outp[(size_t)(n+1)*CH + ch] = __float2bfloat16_rn(t.y*sc + bo);
        outp[(size_t)(n+2)*CH + ch] = __float2bfloat16_rn(t.z*sc + bo);
        outp[(size_t)(n+3)*CH + ch] = __float2bfloat16_rn(t.w*sc + bo);
    }
}

// ---------------- shared GEMM core: C128x128 = A[fp32, M,512] * B^T[bf16, N,512]
// 256 threads, 8 warps (2x4), warp tile 64x32, acc[4][4][4]
#define GPAD 40
__device__ __forceinline__ void gemm_core(const float* __restrict__ Ag,
                                          const __nv_bfloat16* __restrict__ Bg,
                                          __nv_bfloat16* As, __nv_bfloat16* Bs,
                                          float acc[4][4][4]) {
    int tid = threadIdx.x;
    int warp = tid >> 5, lane = tid & 31;
    int g = lane >> 2, t = lane & 3;
    int wm = (warp >> 2) * 64, wn = (warp & 3) * 32;

    for (int k0 = 0; k0 < 512; k0 += 32) {
        {   // A: 128 rows x 32 fp32 -> bf16
            int r = tid >> 3, c = tid & 7;
            #pragma unroll
            for (int it = 0; it < 4; ++it, r += 32) {
                float4 v = *(const float4*)(Ag + (size_t)r*512 + k0 + c*4);
                uint2 pk;
                pk.x = packbf(v.x, v.y);
                pk.y = packbf(v.z, v.w);
                *(uint2*)(As + r*GPAD + c*4) = pk;
            }
        }
        {   // B: 128 rows x 32 bf16
            int r = tid >> 2, c = tid & 3;
            #pragma unroll
            for (int it = 0; it < 2; ++it, r += 64) {
                uint4 v = *(const uint4*)(Bg + (size_t)r*512 + k0 + c*8);
                *(uint4*)(Bs + r*GPAD + c*8) = v;
            }
        }
        __syncthreads();
        #pragma unroll
        for (int ks = 0; ks < 32; ks += 16) {
            uint32_t af[4][4];
            #pragma unroll
            for (int mi = 0; mi < 4; ++mi) {
                const __nv_bfloat16* p = As + (wm + 16*mi + g)*GPAD + ks + 2*t;
                af[mi][0] = ldsu32(p);
                af[mi][1] = ldsu32(p + 8*GPAD);
                af[mi][2] = ldsu32(p + 8);
                af[mi][3] = ldsu32(p + 8*GPAD + 8);
            }
            #pragma unroll
            for (int nj = 0; nj < 4; ++nj) {
                const __nv_bfloat16* p = Bs + (wn + 8*nj + g)*GPAD + ks + 2*t;
                uint32_t b0 = ldsu32(p), b1 = ldsu32(p + 8);
                #pragma unroll
                for (int mi = 0; mi < 4; ++mi)
                    mma16816(acc[mi][nj], af[mi], b0, b1);
            }
        }
        __syncthreads();
    }
}

// ---------------- 2) QKV GEMM ----------------
__global__ __launch_bounds__(256) void gemm_qkv(const float* __restrict__ W,
                                                const float* __restrict__ bias) {
    __shared__ __nv_bfloat16 As[128*GPAD];
    __shared__ __nv_bfloat16 Bs[128*GPAD];
    int z = blockIdx.z;
    int m0 = blockIdx.y * 128, n0 = blockIdx.x * 128;
    float acc[4][4][4] = {};
    gemm_core(W + (size_t)m0*512, g_xn + (size_t)z*HW*CH + (size_t)n0*512, As, Bs, acc);

    int warp = threadIdx.x >> 5, lane = threadIdx.x & 31;
    int g = lane >> 2, t = lane & 3;
    int wm = (warp >> 2) * 64, wn = (warp & 3) * 32;

    #pragma unroll
    for (int mi = 0; mi < 4; ++mi) {
        #pragma unroll
        for (int rr = 0; rr < 2; ++rr) {
            int o = m0 + wm + 16*mi + g + rr*8;
            float bi = bias[o];
            #pragma unroll
            for (int nj = 0; nj < 4; ++nj) {
                int n = n0 + wn + 8*nj + 2*t;
                float v0 = acc[mi][nj][rr*2 + 0] + bi;
                float v1 = acc[mi][nj][rr*2 + 1] + bi;
                if (o < 512) {                 // Q -> [bh][n][d], scaled
                    int h = o >> 6, d = o & 63;
                    size_t base = ((size_t)(z*NH + h)*HW)*HD + d;
                    g_q[base + (size_t)n*HD]     = __float2bfloat16_rn(v0 * QSCALE);
                    g_q[base + (size_t)(n+1)*HD] = __float2bfloat16_rn(v1 * QSCALE);
                } else if (o < 1024) {         // K -> [bh][m][d]
                    int h = (o-512) >> 6, d = (o-512) & 63;
                    size_t base = ((size_t)(z*NH + h)*HW)*HD + d;
                    g_k[base + (size_t)n*HD]     = __float2bfloat16_rn(v0);
                    g_k[base + (size_t)(n+1)*HD] = __float2bfloat16_rn(v1);
                } else {                       // V -> [bh][d][m]
                    int h = (o-1024) >> 6, d = (o-1024) & 63;
                    size_t base = ((size_t)(z*NH + h)*HD + d)*HW + n;
                    *(uint32_t*)&g_v[base] = packbf(v0, v1);
                }
            }
        }
    }
}

// ---------------- 3) flash attention: 128 q rows/CTA, 64-key blocks ------
#define APAD 72
__global__ __launch_bounds__(256) void attn_kernel() {
    __shared__ __nv_bfloat16 Qs[128*APAD];
    __shared__ __nv_bfloat16 Ks[64*APAD];
    __shared__ __nv_bfloat16 Vs[64*APAD];
    int bh = blockIdx.y;
    int n0 = blockIdx.x * 128;
    const __nv_bfloat16* Qg = g_q + ((size_t)bh*HW + n0)*HD;
    const __nv_bfloat16* Kg = g_k + (size_t)bh*HW*HD;
    const __nv_bfloat16* Vg = g_v + (size_t)bh*HD*HW;

    int tid = threadIdx.x;
    int warp = tid >> 5, lane = tid & 31;
    int g = lane >> 2, t = lane & 3;
    int qrow = warp * 16;

    {   // load Q tile (contiguous 16KB)
        int r = tid >> 3, c = tid & 7;
        #pragma unroll
        for (int it = 0; it < 4; ++it, r += 32)
            *(uint4*)(Qs + r*APAD + c*8) = *(const uint4*)(Qg + (size_t)r*HD + c*8);
    }

    float o_acc[8][4] = {};
    float m_lo = -1e30f, m_hi = -1e30f, l_lo = 0.f, l_hi = 0.f;

    for (int kb = 0; kb < 64; ++kb) {
        int m0k = kb * 64;
        __syncthreads();
        {   // K block [64 m][64 d], V block [64 d][64 m]
            int r = tid >> 3, c = tid & 7;
            #pragma unroll
            for (int it = 0; it < 2; ++it) {
                int rr = r + it*32;
                *(uint4*)(Ks + rr*APAD + c*8) =
                    *(const uint4*)(Kg + ((size_t)(m0k + rr))*HD + c*8);
                *(uint4*)(Vs + rr*APAD + c*8) =
                    *(const uint4*)(Vg + (size_t)rr*HW + m0k + c*8);
            }
        }
        __syncthreads();

        // S = Q K^T   (already in log2 units: Q pre-scaled by 0.125*log2 e)
        float s[8][4] = {};
        #pragma unroll
        for (int ks = 0; ks < 4; ++ks) {
            uint32_t af[4];
            const __nv_bfloat16* ap = Qs + (qrow + g)*APAD + ks*16 + 2*t;
            af[0] = ldsu32(ap);
            af[1] = ldsu32(ap + 8*APAD);
            af[2] = ldsu32(ap + 8);
            af[3] = ldsu32(ap + 8*APAD + 8);
            #pragma unroll
            for (int j = 0; j < 8; ++j) {
                const __nv_bfloat16* bp = Ks + (8*j + g)*APAD + ks*16 + 2*t;
                mma16816(s[j], af, ldsu32(bp), ldsu32(bp + 8));
            }
        }

        // online softmax (rows g and g+8 of this warp's 16)
        float mx_lo = -1e30f, mx_hi = -1e30f;
        #pragma unroll
        for (int j = 0; j < 8; ++j) {
            mx_lo = fmaxf(mx_lo, fmaxf(s[j][0], s[j][1]));
            mx_hi = fmaxf(mx_hi, fmaxf(s[j][2], s[j][3]));
        }
        mx_lo = fmaxf(mx_lo, __shfl_xor_sync(0xffffffffu, mx_lo, 1));
        mx_lo = fmaxf(mx_lo, __shfl_xor_sync(0xffffffffu, mx_lo, 2));
        mx_hi = fmaxf(mx_hi, __shfl_xor_sync(0xffffffffu, mx_hi, 1));
        mx_hi = fmaxf(mx_hi, __shfl_xor_sync(0xffffffffu, mx_hi, 2));
        float mn_lo = fmaxf(m_lo, mx_lo), mn_hi = fmaxf(m_hi, mx_hi);
        float al_lo = ex2f(m_lo - mn_lo), al_hi = ex2f(m_hi - mn_hi);
        m_lo = mn_lo; m_hi = mn_hi;

        float rs_lo = 0.f, rs_hi = 0.f;
        #pragma unroll
        for (int j = 0; j < 8; ++j) {
            s[j][0] = ex2f(s[j][0] - m_lo);
            s[j][1] = ex2f(s[j][1] - m_lo);
            s[j][2] = ex2f(s[j][2] - m_hi);
            s[j][3] = ex2f(s[j][3] - m_hi);
            rs_lo += s[j][0] + s[j][1];
            rs_hi += s[j][2] + s[j][3];
        }
        l_lo = l_lo * al_lo + rs_lo;
        l_hi = l_hi * al_hi + rs_hi;
        #pragma unroll
        for (int c = 0; c < 8; ++c) {
            o_acc[c][0] *= al_lo; o_acc[c][1] *= al_lo;
            o_acc[c][2] *= al_hi; o_acc[c][3] *= al_hi;
        }

        // O += P V   (A frags reuse S accum layout)
        #pragma unroll
        for (int ks = 0; ks < 4; ++ks) {
            uint32_t pa[4];
            pa[0] = packbf(s[2*ks][0],   s[2*ks][1]);
            pa[1] = packbf(s[2*ks][2],   s[2*ks][3]);
            pa[2] = packbf(s[2*ks+1][0], s[2*ks+1][1]);
            pa[3] = packbf(s[2*ks+1][2], s[2*ks+1][3]);
            #pragma unroll
            for (int c = 0; c < 8; ++c) {
                const __nv_bfloat16* bp = Vs + (8*c + g)*APAD + ks*16 + 2*t;
                mma16816(o_acc[c], pa, ldsu32(bp), ldsu32(bp + 8));
            }
        }
    }

    // finalize
    l_lo += __shfl_xor_sync(0xffffffffu, l_lo, 1);
    l_lo += __shfl_xor_sync(0xffffffffu, l_lo, 2);
    l_hi += __shfl_xor_sync(0xffffffffu, l_hi, 1);
    l_hi += __shfl_xor_sync(0xffffffffu, l_hi, 2);
    float inv_lo = 1.f / l_lo, inv_hi = 1.f / l_hi;

    int b = bh >> 3, h = bh & 7;
    int r_lo = n0 + qrow + g, r_hi = r_lo + 8;
    __nv_bfloat16* Og = g_o + (size_t)b*HW*CH;
    #pragma unroll
    for (int c = 0; c < 8; ++c) {
        int col = h*64 + 8*c + 2*t;
        *(uint32_t*)(Og + (size_t)r_lo*CH + col) =
            packbf(o_acc[c][0]*inv_lo, o_acc[c][1]*inv_lo);
        *(uint32_t*)(Og + (size_t)r_hi*CH + col) =
            packbf(o_acc[c][2]*inv_hi, o_acc[c][3]*inv_hi);
    }
}

// ---------------- 4) proj GEMM + bias + residual ----------------
__global__ __launch_bounds__(256) void gemm_proj(const float* __restrict__ W,
                                                 const float* __restrict__ bias,
                                                 const float* __restrict__ x,
                                                 float* __restrict__ out) {
    __shared__ __nv_bfloat16 As[128*GPAD];
    __shared__ __nv_bfloat16 Bs[128*GPAD];
    int z = blockIdx.z;
    int m0 = blockIdx.y * 128, n0 = blockIdx.x * 128;
    float acc[4][4][4] = {};
    gemm_core(W + (size_t)m0*512, g_o + (size_t)z*HW*CH + (size_t)n0*512, As, Bs, acc);

    int warp = threadIdx.x >> 5, lane = threadIdx.x & 31;
    int g = lane >> 2, t = lane & 3;
    int wm = (warp >> 2) * 64, wn = (warp & 3) * 32;

    #pragma unroll
    for (int mi = 0; mi < 4; ++mi) {
        #pragma unroll
        for (int rr = 0; rr < 2; ++rr) {
            int c = m0 + wm + 16*mi + g + rr*8;
            float bi = bias[c];
            size_t rowb = ((size_t)z*CH + c)*HW;
            #pragma unroll
            for (int nj = 0; nj < 4; ++nj) {
                int n = n0 + wn + 8*nj + 2*t;
                float2 xr = *(const float2*)(x + rowb + n);
                float2 o;
                o.x = acc[mi][nj][rr*2 + 0] + bi + xr.x;
                o.y = acc[mi][nj][rr*2 + 1] + bi + xr.y;
                *(float2*)(out + rowb + n) = o;
            }
        }
    }
}

// ---------------- launch ----------------
extern "C" void kernel_launch(void* const* d_in, const int* in_sizes, int n_in,
                              void* d_out, int out_size) {
    const float* x      = (const float*)d_in[0];
    const float* norm_w = (const float*)d_in[1];
    const float* norm_b = (const float*)d_in[2];
    const float* qkv_w  = (const float*)d_in[3];
    const float* qkv_b  = (const float*)d_in[4];
    const float* proj_w = (const float*)d_in[5];
    const float* proj_b = (const float*)d_in[6];
    float* out = (float*)d_out;

    gn_kernel<<<BATCH*NG, 512>>>(x, norm_w, norm_b);
    gemm_qkv<<<dim3(HW/128, 12, BATCH), 256>>>(qkv_w, qkv_b);
    attn_kernel<<<dim3(HW/128, BATCH*NH), 256>>>();
    gemm_proj<<<dim3(HW/128, 4, BATCH), 256>>>(proj_w, proj_b, x, out);
}